// round 1
// baseline (speedup 1.0000x reference)
#include <cuda_runtime.h>
#include <math.h>

#define Bx  16
#define Sx  512
#define Vx  512
#define Hx  1024
#define NLx 8
#define NHx 16
#define DHx 64
#define Fx  4096
#define Mx  (Bx*Sx)   // 8192 rows of activations

// ---------------- scratch (no allocations allowed) ----------------
__device__ float g_x[Mx*Hx];
__device__ float g_h[Mx*Hx];
__device__ float g_qkv[Mx*3*Hx];
__device__ float g_attn[Mx*Hx];
__device__ float g_mid[(size_t)Mx*Fx];
__device__ float g_scores[(size_t)Bx*NHx*Sx*Sx];   // 256 MB

// ---------------- embedding gather ----------------
__global__ __launch_bounds__(256) void embed_kernel(const int* __restrict__ ids,
                                                    const float* __restrict__ emb,
                                                    float* __restrict__ out) {
    int m = blockIdx.x, t = threadIdx.x;
    int id = ids[m];
    const float4* src = (const float4*)(emb + (size_t)id * Hx);
    float4* dst = (float4*)(out + (size_t)m * Hx);
    dst[t] = src[t];   // 256 threads * float4 = 1024 floats
}

// ---------------- layernorm (row = 1024) ----------------
__global__ __launch_bounds__(256) void ln_kernel(const float* __restrict__ x,
                                                 const float* __restrict__ g,
                                                 const float* __restrict__ b,
                                                 float* __restrict__ out) {
    int m = blockIdx.x, t = threadIdx.x;
    __shared__ float red[8];
    float4 v = ((const float4*)(x + (size_t)m * Hx))[t];

    float s = v.x + v.y + v.z + v.w;
#pragma unroll
    for (int o = 16; o; o >>= 1) s += __shfl_xor_sync(0xffffffffu, s, o);
    if ((t & 31) == 0) red[t >> 5] = s;
    __syncthreads();
    float mu = 0.f;
#pragma unroll
    for (int w = 0; w < 8; w++) mu += red[w];
    mu *= (1.0f / Hx);
    __syncthreads();

    float d0 = v.x - mu, d1 = v.y - mu, d2 = v.z - mu, d3 = v.w - mu;
    float s2 = d0*d0 + d1*d1 + d2*d2 + d3*d3;
#pragma unroll
    for (int o = 16; o; o >>= 1) s2 += __shfl_xor_sync(0xffffffffu, s2, o);
    if ((t & 31) == 0) red[t >> 5] = s2;
    __syncthreads();
    float var = 0.f;
#pragma unroll
    for (int w = 0; w < 8; w++) var += red[w];
    var *= (1.0f / Hx);
    float inv = rsqrtf(var + 1e-5f);

    float4 gg = ((const float4*)g)[t];
    float4 bb = ((const float4*)b)[t];
    float4 o4;
    o4.x = d0 * inv * gg.x + bb.x;
    o4.y = d1 * inv * gg.y + bb.y;
    o4.z = d2 * inv * gg.z + bb.z;
    o4.w = d3 * inv * gg.w + bb.w;
    ((float4*)(out + (size_t)m * Hx))[t] = o4;
}

// ---------------- generic tiled fp32 GEMM: C = f(A@W + bias) (+ resid) ----------------
// A: [M,K] row-major. W: [K,N] (or [N,K] if TRANSB). 64x64 tile, BK=16, 4x4 microtile.
__device__ __forceinline__ float gelu_f(float v) {
    return 0.5f * v * (1.0f + tanhf(0.7978845608028654f * (v + 0.044715f * v * v * v)));
}

template<bool TRANSB, bool GELU, bool RESID>
__global__ __launch_bounds__(256) void gemm_kernel(const float* __restrict__ A,
                                                   const float* __restrict__ W,
                                                   const float* __restrict__ bias,
                                                   const float* __restrict__ R,
                                                   float* __restrict__ C,
                                                   int M, int N, int K) {
    const int t = threadIdx.x;
    const int n0 = blockIdx.x * 64, m0 = blockIdx.y * 64;
    __shared__ float As[16 * 68];
    __shared__ float Bs[16 * 68];
    const int ty = t >> 4, tx = t & 15;
    float acc[4][4] = {};

    for (int k0 = 0; k0 < K; k0 += 16) {
        {   // A tile -> As[k][m] (transposed scalar stores)
            int row = t >> 2, kv = (t & 3) * 4;
            float4 a = *(const float4*)(A + (size_t)(m0 + row) * K + k0 + kv);
            As[(kv + 0) * 68 + row] = a.x;
            As[(kv + 1) * 68 + row] = a.y;
            As[(kv + 2) * 68 + row] = a.z;
            As[(kv + 3) * 68 + row] = a.w;
        }
        if (!TRANSB) {   // W[k][n] -> Bs[k][n], vector store
            int kk = t >> 4, nv = (t & 15) * 4;
            *(float4*)&Bs[kk * 68 + nv] =
                *(const float4*)(W + (size_t)(k0 + kk) * N + n0 + nv);
        } else {         // W[n][k] -> Bs[k][n]
            int row = t >> 2, kv = (t & 3) * 4;
            float4 bq = *(const float4*)(W + (size_t)(n0 + row) * K + k0 + kv);
            Bs[(kv + 0) * 68 + row] = bq.x;
            Bs[(kv + 1) * 68 + row] = bq.y;
            Bs[(kv + 2) * 68 + row] = bq.z;
            Bs[(kv + 3) * 68 + row] = bq.w;
        }
        __syncthreads();
#pragma unroll
        for (int k = 0; k < 16; k++) {
            float4 a = *(const float4*)&As[k * 68 + ty * 4];
            float4 bv = *(const float4*)&Bs[k * 68 + tx * 4];
            acc[0][0] += a.x * bv.x; acc[0][1] += a.x * bv.y; acc[0][2] += a.x * bv.z; acc[0][3] += a.x * bv.w;
            acc[1][0] += a.y * bv.x; acc[1][1] += a.y * bv.y; acc[1][2] += a.y * bv.z; acc[1][3] += a.y * bv.w;
            acc[2][0] += a.z * bv.x; acc[2][1] += a.z * bv.y; acc[2][2] += a.z * bv.z; acc[2][3] += a.z * bv.w;
            acc[3][0] += a.w * bv.x; acc[3][1] += a.w * bv.y; acc[3][2] += a.w * bv.z; acc[3][3] += a.w * bv.w;
        }
        __syncthreads();
    }

#pragma unroll
    for (int i = 0; i < 4; i++) {
        int m = m0 + ty * 4 + i;
#pragma unroll
        for (int j = 0; j < 4; j++) {
            int n = n0 + tx * 4 + j;
            float val = acc[i][j];
            if (bias) val += bias[n];
            if (GELU) val = gelu_f(val);
            if (RESID) val += R[(size_t)m * N + n];
            C[(size_t)m * N + n] = val;
        }
    }
}

// ---------------- attention scores: sc = scale*(q.kT) + alibi/mask bias ----------------
__global__ __launch_bounds__(256) void scores_kernel(const float* __restrict__ qkv,
                                                     const int* __restrict__ sp,
                                                     float* __restrict__ sc) {
    int jt = blockIdx.x;          // 8 tiles of 64 keys
    int it = blockIdx.y;          // 16 tiles of 32 queries
    int bn = blockIdx.z;          // 256 (b, head)
    int b = bn >> 4, n = bn & 15;
    int t = threadIdx.x;
    __shared__ float Qs[32 * 68];
    __shared__ float Ks[64 * 68];
    int i0 = it * 32, j0 = jt * 64;

#pragma unroll
    for (int l = 0; l < 8; l++) {
        int e = t + l * 256;
        int i = e >> 6, d = e & 63;
        Qs[i * 68 + d] = qkv[(size_t)(b * Sx + i0 + i) * 3072 + n * 64 + d];
    }
#pragma unroll
    for (int l = 0; l < 16; l++) {
        int e = t + l * 256;
        int j = e >> 6, d = e & 63;
        Ks[j * 68 + d] = qkv[(size_t)(b * Sx + j0 + j) * 3072 + 1024 + n * 64 + d];
    }
    __syncthreads();

    int trow = t >> 4, tj = t & 15;
    int ia = trow * 2, ib = ia + 1;
    float acc[2][4] = {};
#pragma unroll
    for (int dq = 0; dq < 16; dq++) {
        float4 q0 = *(const float4*)&Qs[ia * 68 + dq * 4];
        float4 q1 = *(const float4*)&Qs[ib * 68 + dq * 4];
#pragma unroll
        for (int jj = 0; jj < 4; jj++) {
            float4 kv = *(const float4*)&Ks[(tj * 4 + jj) * 68 + dq * 4];
            acc[0][jj] += q0.x * kv.x + q0.y * kv.y + q0.z * kv.z + q0.w * kv.w;
            acc[1][jj] += q1.x * kv.x + q1.y * kv.y + q1.z * kv.z + q1.w * kv.w;
        }
    }

    float slope = exp2f(-0.5f * (float)(n + 1));
    int spv = sp[b];
    const float scale = 0.125f;   // 1/sqrt(64)
#pragma unroll
    for (int r = 0; r < 2; r++) {
        int i = i0 + ia + r;
        float4 o4;
        float* oc = &o4.x;
#pragma unroll
        for (int jj = 0; jj < 4; jj++) {
            int j = j0 + tj * 4 + jj;
            bool allowed = (j <= i) && !((i >= spv) && (j < spv));
            float bias = allowed ? (-slope * (float)(i - j)) : -1e9f;
            oc[jj] = acc[r][jj] * scale + bias;
        }
        *(float4*)(sc + ((size_t)bn * Sx + i) * Sx + j0 + tj * 4) = o4;
    }
}

// ---------------- softmax over last dim (512), one warp per row ----------------
__global__ __launch_bounds__(256) void softmax_kernel(float* __restrict__ sc) {
    int row = blockIdx.x * 8 + (threadIdx.x >> 5);
    int lane = threadIdx.x & 31;
    float* p = sc + (size_t)row * Sx;
    float4 v[4];
    float mx = -1e30f;
#pragma unroll
    for (int l = 0; l < 4; l++) {
        v[l] = ((float4*)p)[lane + l * 32];
        mx = fmaxf(mx, fmaxf(fmaxf(v[l].x, v[l].y), fmaxf(v[l].z, v[l].w)));
    }
#pragma unroll
    for (int o = 16; o; o >>= 1) mx = fmaxf(mx, __shfl_xor_sync(0xffffffffu, mx, o));
    float s = 0.f;
#pragma unroll
    for (int l = 0; l < 4; l++) {
        v[l].x = expf(v[l].x - mx); v[l].y = expf(v[l].y - mx);
        v[l].z = expf(v[l].z - mx); v[l].w = expf(v[l].w - mx);
        s += v[l].x + v[l].y + v[l].z + v[l].w;
    }
#pragma unroll
    for (int o = 16; o; o >>= 1) s += __shfl_xor_sync(0xffffffffu, s, o);
    float inv = 1.0f / s;
#pragma unroll
    for (int l = 0; l < 4; l++) {
        v[l].x *= inv; v[l].y *= inv; v[l].z *= inv; v[l].w *= inv;
        ((float4*)p)[lane + l * 32] = v[l];
    }
}

// ---------------- PV: attn[b,i,n*64+d] = sum_j P[b,n,i,j] * V[b,j,n,d] ----------------
__global__ __launch_bounds__(256) void pv_kernel(const float* __restrict__ sc,
                                                 const float* __restrict__ qkv,
                                                 float* __restrict__ attn) {
    int it = blockIdx.x;        // 8 tiles of 64 queries
    int bn = blockIdx.y;        // 256
    int b = bn >> 4, n = bn & 15;
    int t = threadIdx.x;
    __shared__ float Ps[64 * 68];   // [j][i]
    __shared__ float Vs[64 * 68];   // [j][d]
    const int ty = t >> 4, tx = t & 15;
    float acc[4][4] = {};
    int i0 = it * 64;

    for (int j0 = 0; j0 < Sx; j0 += 64) {
#pragma unroll
        for (int l = 0; l < 16; l++) {
            int e = t + l * 256;
            int i = e >> 6, j = e & 63;
            Ps[j * 68 + i] = sc[((size_t)bn * Sx + i0 + i) * Sx + j0 + j];
        }
#pragma unroll
        for (int l = 0; l < 16; l++) {
            int e = t + l * 256;
            int j = e >> 6, d = e & 63;
            Vs[j * 68 + d] = qkv[(size_t)(b * Sx + j0 + j) * 3072 + 2048 + n * 64 + d];
        }
        __syncthreads();
#pragma unroll 8
        for (int j = 0; j < 64; j++) {
            float4 p = *(const float4*)&Ps[j * 68 + ty * 4];
            float4 vv = *(const float4*)&Vs[j * 68 + tx * 4];
            acc[0][0] += p.x * vv.x; acc[0][1] += p.x * vv.y; acc[0][2] += p.x * vv.z; acc[0][3] += p.x * vv.w;
            acc[1][0] += p.y * vv.x; acc[1][1] += p.y * vv.y; acc[1][2] += p.y * vv.z; acc[1][3] += p.y * vv.w;
            acc[2][0] += p.z * vv.x; acc[2][1] += p.z * vv.y; acc[2][2] += p.z * vv.z; acc[2][3] += p.z * vv.w;
            acc[3][0] += p.w * vv.x; acc[3][1] += p.w * vv.y; acc[3][2] += p.w * vv.z; acc[3][3] += p.w * vv.w;
        }
        __syncthreads();
    }

#pragma unroll
    for (int i = 0; i < 4; i++) {
#pragma unroll
        for (int j = 0; j < 4; j++) {
            attn[(size_t)(b * Sx + i0 + ty * 4 + i) * Hx + n * 64 + tx * 4 + j] = acc[i][j];
        }
    }
}

// ---------------- launcher ----------------
extern "C" void kernel_launch(void* const* d_in, const int* in_sizes, int n_in,
                              void* d_out, int out_size) {
    const int*   ids    = (const int*)d_in[0];
    const int*   sp     = (const int*)d_in[1];
    const float* emb    = (const float*)d_in[2];
    const float* ln1_g  = (const float*)d_in[3];
    const float* ln1_b  = (const float*)d_in[4];
    const float* Wqkv   = (const float*)d_in[5];
    const float* bqkv   = (const float*)d_in[6];
    const float* Wo     = (const float*)d_in[7];
    const float* bo     = (const float*)d_in[8];
    const float* ln2_g  = (const float*)d_in[9];
    const float* ln2_b  = (const float*)d_in[10];
    const float* Wfc    = (const float*)d_in[11];
    const float* bfc    = (const float*)d_in[12];
    const float* Wproj  = (const float*)d_in[13];
    const float* bproj  = (const float*)d_in[14];
    const float* lnf_g  = (const float*)d_in[15];
    const float* lnf_b  = (const float*)d_in[16];
    float* out = (float*)d_out;

    float *x, *h, *qkv, *attn, *mid, *scores;
    cudaGetSymbolAddress((void**)&x,      g_x);
    cudaGetSymbolAddress((void**)&h,      g_h);
    cudaGetSymbolAddress((void**)&qkv,    g_qkv);
    cudaGetSymbolAddress((void**)&attn,   g_attn);
    cudaGetSymbolAddress((void**)&mid,    g_mid);
    cudaGetSymbolAddress((void**)&scores, g_scores);

    embed_kernel<<<Mx, 256>>>(ids, emb, x);

    for (int l = 0; l < NLx; l++) {
        ln_kernel<<<Mx, 256>>>(x, ln1_g + l * Hx, ln1_b + l * Hx, h);
        gemm_kernel<false, false, false><<<dim3(3 * Hx / 64, Mx / 64), 256>>>(
            h, Wqkv + (size_t)l * Hx * 3 * Hx, bqkv + (size_t)l * 3 * Hx, nullptr, qkv,
            Mx, 3 * Hx, Hx);
        scores_kernel<<<dim3(8, 16, 256), 256>>>(qkv, sp, scores);
        softmax_kernel<<<(Bx * NHx * Sx) / 8, 256>>>(scores);
        pv_kernel<<<dim3(8, 256), 256>>>(scores, qkv, attn);
        gemm_kernel<false, false, true><<<dim3(Hx / 64, Mx / 64), 256>>>(
            attn, Wo + (size_t)l * Hx * Hx, bo + (size_t)l * Hx, x, x, Mx, Hx, Hx);
        ln_kernel<<<Mx, 256>>>(x, ln2_g + l * Hx, ln2_b + l * Hx, h);
        gemm_kernel<false, true, false><<<dim3(Fx / 64, Mx / 64), 256>>>(
            h, Wfc + (size_t)l * Hx * Fx, bfc + (size_t)l * Fx, nullptr, mid,
            Mx, Fx, Hx);
        gemm_kernel<false, false, true><<<dim3(Hx / 64, Mx / 64), 256>>>(
            mid, Wproj + (size_t)l * Fx * Hx, bproj + (size_t)l * Hx, x, x, Mx, Hx, Fx);
    }

    ln_kernel<<<Mx, 256>>>(x, lnf_g, lnf_b, h);
    gemm_kernel<true, false, false><<<dim3(Vx / 64, Mx / 64), 256>>>(
        h, emb, nullptr, nullptr, out, Mx, Vx, Hx);
}

// round 2
// speedup vs baseline: 2.2067x; 2.2067x over previous
#include <cuda_runtime.h>
#include <math.h>
#include <stdint.h>

#define Bx  16
#define Sx  512
#define Vx  512
#define Hx  1024
#define NLx 8
#define NHx 16
#define DHx 64
#define Fx  4096
#define Mx  (Bx*Sx)   // 8192 rows of activations

// ---------------- scratch (no allocations allowed) ----------------
__device__ float g_x[Mx*Hx];
__device__ float g_h[Mx*Hx];
__device__ float g_qkv[Mx*3*Hx];
__device__ float g_attn[Mx*Hx];
__device__ float g_mid[(size_t)Mx*Fx];
__device__ float g_scores[(size_t)Bx*NHx*Sx*Sx];   // 256 MB

// ---------------- helpers ----------------
__device__ __forceinline__ float to_tf32(float x) {
    float r;
    asm("cvt.rna.tf32.f32 %0, %1;" : "=f"(r) : "f"(x));
    return r;
}

__device__ __forceinline__ void mma_tf32(float* c, const uint32_t* a, const uint32_t* b) {
    asm volatile(
        "mma.sync.aligned.m16n8k8.row.col.f32.tf32.tf32.f32 "
        "{%0,%1,%2,%3}, {%4,%5,%6,%7}, {%8,%9}, {%0,%1,%2,%3};\n"
        : "+f"(c[0]), "+f"(c[1]), "+f"(c[2]), "+f"(c[3])
        : "r"(a[0]), "r"(a[1]), "r"(a[2]), "r"(a[3]), "r"(b[0]), "r"(b[1]));
}

__device__ __forceinline__ float gelu_f(float v) {
    return 0.5f * v * (1.0f + tanhf(0.7978845608028654f * (v + 0.044715f * v * v * v)));
}

// ---------------- embedding gather ----------------
__global__ __launch_bounds__(256) void embed_kernel(const int* __restrict__ ids,
                                                    const float* __restrict__ emb,
                                                    float* __restrict__ out) {
    int m = blockIdx.x, t = threadIdx.x;
    int id = ids[m];
    const float4* src = (const float4*)(emb + (size_t)id * Hx);
    float4* dst = (float4*)(out + (size_t)m * Hx);
    dst[t] = src[t];
}

// ---------------- layernorm (row = 1024) ----------------
__global__ __launch_bounds__(256) void ln_kernel(const float* __restrict__ x,
                                                 const float* __restrict__ g,
                                                 const float* __restrict__ b,
                                                 float* __restrict__ out) {
    int m = blockIdx.x, t = threadIdx.x;
    __shared__ float red[8];
    float4 v = ((const float4*)(x + (size_t)m * Hx))[t];

    float s = v.x + v.y + v.z + v.w;
#pragma unroll
    for (int o = 16; o; o >>= 1) s += __shfl_xor_sync(0xffffffffu, s, o);
    if ((t & 31) == 0) red[t >> 5] = s;
    __syncthreads();
    float mu = 0.f;
#pragma unroll
    for (int w = 0; w < 8; w++) mu += red[w];
    mu *= (1.0f / Hx);
    __syncthreads();

    float d0 = v.x - mu, d1 = v.y - mu, d2 = v.z - mu, d3 = v.w - mu;
    float s2 = d0*d0 + d1*d1 + d2*d2 + d3*d3;
#pragma unroll
    for (int o = 16; o; o >>= 1) s2 += __shfl_xor_sync(0xffffffffu, s2, o);
    if ((t & 31) == 0) red[t >> 5] = s2;
    __syncthreads();
    float var = 0.f;
#pragma unroll
    for (int w = 0; w < 8; w++) var += red[w];
    var *= (1.0f / Hx);
    float inv = rsqrtf(var + 1e-5f);

    float4 gg = ((const float4*)g)[t];
    float4 bb = ((const float4*)b)[t];
    float4 o4;
    o4.x = d0 * inv * gg.x + bb.x;
    o4.y = d1 * inv * gg.y + bb.y;
    o4.z = d2 * inv * gg.z + bb.z;
    o4.w = d3 * inv * gg.w + bb.w;
    ((float4*)(out + (size_t)m * Hx))[t] = o4;
}

// ---------------- tf32 tensor-core GEMM: C = f(A@W + bias) (+ resid) --------
// A: [M,K] row-major. W: [K,N] (or [N,K] if TRANSB). CTA tile 128x128x32.
// 8 warps, each 32x64 (2x8 m16n8k8 frags). tf32 cvt during smem fill.
#define APAD 36    // As stride: banks (4g+q) distinct for frag loads
#define BPAD 136   // Bs stride: banks (8q+g) distinct for frag loads

template<bool TRANSB, bool GELU, bool RESID>
__global__ __launch_bounds__(256) void gemm_mma(const float* __restrict__ A,
                                                const float* __restrict__ W,
                                                const float* __restrict__ bias,
                                                const float* __restrict__ R,
                                                float* __restrict__ C,
                                                int M, int N, int K) {
    __shared__ float As[128 * APAD];
    __shared__ float Bs[32 * BPAD];

    const int t = threadIdx.x;
    const int warp = t >> 5, lane = t & 31;
    const int g = lane >> 2, q = lane & 3;
    const int wm = warp >> 1;        // 0..3  -> m offset wm*32
    const int wn = warp & 1;         // 0..1  -> n offset wn*64
    const int m0 = blockIdx.y * 128, n0 = blockIdx.x * 128;

    float acc[2][8][4];
#pragma unroll
    for (int mt = 0; mt < 2; mt++)
#pragma unroll
        for (int nt = 0; nt < 8; nt++)
#pragma unroll
            for (int r = 0; r < 4; r++) acc[mt][nt][r] = 0.f;

    for (int k0 = 0; k0 < K; k0 += 32) {
        // ---- A tile: [128 rows][32 k] -> As[m][k]
        {
            int rb = t >> 3, c4 = (t & 7) * 4;
#pragma unroll
            for (int p = 0; p < 4; p++) {
                int row = rb + p * 32;
                float4 a = *(const float4*)(A + (size_t)(m0 + row) * K + k0 + c4);
                a.x = to_tf32(a.x); a.y = to_tf32(a.y);
                a.z = to_tf32(a.z); a.w = to_tf32(a.w);
                *(float4*)&As[row * APAD + c4] = a;
            }
        }
        // ---- B tile -> Bs[k][n]
        if (!TRANSB) {
            int rb = t >> 5, c = (t & 31) * 4;
#pragma unroll
            for (int p = 0; p < 4; p++) {
                int kr = rb + p * 8;
                float4 b = *(const float4*)(W + (size_t)(k0 + kr) * N + n0 + c);
                b.x = to_tf32(b.x); b.y = to_tf32(b.y);
                b.z = to_tf32(b.z); b.w = to_tf32(b.w);
                *(float4*)&Bs[kr * BPAD + c] = b;
            }
        } else {
            int nb = t >> 3, kc = (t & 7) * 4;
#pragma unroll
            for (int p = 0; p < 4; p++) {
                int nr = nb + p * 32;
                float4 b = *(const float4*)(W + (size_t)(n0 + nr) * K + k0 + kc);
                Bs[(kc + 0) * BPAD + nr] = to_tf32(b.x);
                Bs[(kc + 1) * BPAD + nr] = to_tf32(b.y);
                Bs[(kc + 2) * BPAD + nr] = to_tf32(b.z);
                Bs[(kc + 3) * BPAD + nr] = to_tf32(b.w);
            }
        }
        __syncthreads();

#pragma unroll
        for (int ks = 0; ks < 4; ks++) {
            const int k = ks * 8;
            uint32_t af[2][4], bf[8][2];
#pragma unroll
            for (int mt = 0; mt < 2; mt++) {
                int r = wm * 32 + mt * 16 + g;
                af[mt][0] = __float_as_uint(As[(r    ) * APAD + k + q]);
                af[mt][1] = __float_as_uint(As[(r + 8) * APAD + k + q]);
                af[mt][2] = __float_as_uint(As[(r    ) * APAD + k + q + 4]);
                af[mt][3] = __float_as_uint(As[(r + 8) * APAD + k + q + 4]);
            }
#pragma unroll
            for (int nt = 0; nt < 8; nt++) {
                int n = wn * 64 + nt * 8 + g;
                bf[nt][0] = __float_as_uint(Bs[(k + q    ) * BPAD + n]);
                bf[nt][1] = __float_as_uint(Bs[(k + q + 4) * BPAD + n]);
            }
#pragma unroll
            for (int mt = 0; mt < 2; mt++)
#pragma unroll
                for (int nt = 0; nt < 8; nt++)
                    mma_tf32(acc[mt][nt], af[mt], bf[nt]);
        }
        __syncthreads();
    }

    // ---- epilogue
#pragma unroll
    for (int mt = 0; mt < 2; mt++) {
#pragma unroll
        for (int nt = 0; nt < 8; nt++) {
            int r0 = m0 + wm * 32 + mt * 16 + g;
            int c0 = n0 + wn * 64 + nt * 8 + q * 2;
            float b0 = bias ? bias[c0] : 0.f;
            float b1 = bias ? bias[c0 + 1] : 0.f;
#pragma unroll
            for (int half = 0; half < 2; half++) {
                int row = r0 + half * 8;
                float v0 = acc[mt][nt][half * 2 + 0] + b0;
                float v1 = acc[mt][nt][half * 2 + 1] + b1;
                if (GELU) { v0 = gelu_f(v0); v1 = gelu_f(v1); }
                if (RESID) {
                    const float2 rr = *(const float2*)(R + (size_t)row * N + c0);
                    v0 += rr.x; v1 += rr.y;
                }
                float2 o2; o2.x = v0; o2.y = v1;
                *(float2*)(C + (size_t)row * N + c0) = o2;
            }
        }
    }
}

// ---------------- attention scores: sc = scale*(q.kT) + alibi/mask bias ----------------
__global__ __launch_bounds__(256) void scores_kernel(const float* __restrict__ qkv,
                                                     const int* __restrict__ sp,
                                                     float* __restrict__ sc) {
    int jt = blockIdx.x;          // 8 tiles of 64 keys
    int it = blockIdx.y;          // 16 tiles of 32 queries
    int bn = blockIdx.z;          // 256 (b, head)
    int b = bn >> 4, n = bn & 15;
    int t = threadIdx.x;
    __shared__ float Qs[32 * 68];
    __shared__ float Ks[64 * 68];
    int i0 = it * 32, j0 = jt * 64;

#pragma unroll
    for (int l = 0; l < 8; l++) {
        int e = t + l * 256;
        int i = e >> 6, d = e & 63;
        Qs[i * 68 + d] = qkv[(size_t)(b * Sx + i0 + i) * 3072 + n * 64 + d];
    }
#pragma unroll
    for (int l = 0; l < 16; l++) {
        int e = t + l * 256;
        int j = e >> 6, d = e & 63;
        Ks[j * 68 + d] = qkv[(size_t)(b * Sx + j0 + j) * 3072 + 1024 + n * 64 + d];
    }
    __syncthreads();

    int trow = t >> 4, tj = t & 15;
    int ia = trow * 2, ib = ia + 1;
    float acc[2][4] = {};
#pragma unroll
    for (int dq = 0; dq < 16; dq++) {
        float4 q0 = *(const float4*)&Qs[ia * 68 + dq * 4];
        float4 q1 = *(const float4*)&Qs[ib * 68 + dq * 4];
#pragma unroll
        for (int jj = 0; jj < 4; jj++) {
            float4 kv = *(const float4*)&Ks[(tj * 4 + jj) * 68 + dq * 4];
            acc[0][jj] += q0.x * kv.x + q0.y * kv.y + q0.z * kv.z + q0.w * kv.w;
            acc[1][jj] += q1.x * kv.x + q1.y * kv.y + q1.z * kv.z + q1.w * kv.w;
        }
    }

    float slope = exp2f(-0.5f * (float)(n + 1));
    int spv = sp[b];
    const float scale = 0.125f;   // 1/sqrt(64)
#pragma unroll
    for (int r = 0; r < 2; r++) {
        int i = i0 + ia + r;
        float4 o4;
        float* oc = &o4.x;
#pragma unroll
        for (int jj = 0; jj < 4; jj++) {
            int j = j0 + tj * 4 + jj;
            bool allowed = (j <= i) && !((i >= spv) && (j < spv));
            float bias = allowed ? (-slope * (float)(i - j)) : -1e9f;
            oc[jj] = acc[r][jj] * scale + bias;
        }
        *(float4*)(sc + ((size_t)bn * Sx + i) * Sx + j0 + tj * 4) = o4;
    }
}

// ---------------- softmax over last dim (512), one warp per row ----------------
__global__ __launch_bounds__(256) void softmax_kernel(float* __restrict__ sc) {
    int row = blockIdx.x * 8 + (threadIdx.x >> 5);
    int lane = threadIdx.x & 31;
    float* p = sc + (size_t)row * Sx;
    float4 v[4];
    float mx = -1e30f;
#pragma unroll
    for (int l = 0; l < 4; l++) {
        v[l] = ((float4*)p)[lane + l * 32];
        mx = fmaxf(mx, fmaxf(fmaxf(v[l].x, v[l].y), fmaxf(v[l].z, v[l].w)));
    }
#pragma unroll
    for (int o = 16; o; o >>= 1) mx = fmaxf(mx, __shfl_xor_sync(0xffffffffu, mx, o));
    float s = 0.f;
#pragma unroll
    for (int l = 0; l < 4; l++) {
        v[l].x = expf(v[l].x - mx); v[l].y = expf(v[l].y - mx);
        v[l].z = expf(v[l].z - mx); v[l].w = expf(v[l].w - mx);
        s += v[l].x + v[l].y + v[l].z + v[l].w;
    }
#pragma unroll
    for (int o = 16; o; o >>= 1) s += __shfl_xor_sync(0xffffffffu, s, o);
    float inv = 1.0f / s;
#pragma unroll
    for (int l = 0; l < 4; l++) {
        v[l].x *= inv; v[l].y *= inv; v[l].z *= inv; v[l].w *= inv;
        ((float4*)p)[lane + l * 32] = v[l];
    }
}

// ---------------- PV: attn[b,i,n*64+d] = sum_j P[b,n,i,j] * V[b,j,n,d] ----------------
__global__ __launch_bounds__(256) void pv_kernel(const float* __restrict__ sc,
                                                 const float* __restrict__ qkv,
                                                 float* __restrict__ attn) {
    int it = blockIdx.x;        // 8 tiles of 64 queries
    int bn = blockIdx.y;        // 256
    int b = bn >> 4, n = bn & 15;
    int t = threadIdx.x;
    __shared__ float Ps[64 * 68];   // [j][i]
    __shared__ float Vs[64 * 68];   // [j][d]
    const int ty = t >> 4, tx = t & 15;
    float acc[4][4] = {};
    int i0 = it * 64;

    for (int j0 = 0; j0 < Sx; j0 += 64) {
#pragma unroll
        for (int l = 0; l < 16; l++) {
            int e = t + l * 256;
            int i = e >> 6, j = e & 63;
            Ps[j * 68 + i] = sc[((size_t)bn * Sx + i0 + i) * Sx + j0 + j];
        }
#pragma unroll
        for (int l = 0; l < 16; l++) {
            int e = t + l * 256;
            int j = e >> 6, d = e & 63;
            Vs[j * 68 + d] = qkv[(size_t)(b * Sx + j0 + j) * 3072 + 2048 + n * 64 + d];
        }
        __syncthreads();
#pragma unroll 8
        for (int j = 0; j < 64; j++) {
            float4 p = *(const float4*)&Ps[j * 68 + ty * 4];
            float4 vv = *(const float4*)&Vs[j * 68 + tx * 4];
            acc[0][0] += p.x * vv.x; acc[0][1] += p.x * vv.y; acc[0][2] += p.x * vv.z; acc[0][3] += p.x * vv.w;
            acc[1][0] += p.y * vv.x; acc[1][1] += p.y * vv.y; acc[1][2] += p.y * vv.z; acc[1][3] += p.y * vv.w;
            acc[2][0] += p.z * vv.x; acc[2][1] += p.z * vv.y; acc[2][2] += p.z * vv.z; acc[2][3] += p.z * vv.w;
            acc[3][0] += p.w * vv.x; acc[3][1] += p.w * vv.y; acc[3][2] += p.w * vv.z; acc[3][3] += p.w * vv.w;
        }
        __syncthreads();
    }

#pragma unroll
    for (int i = 0; i < 4; i++) {
#pragma unroll
        for (int j = 0; j < 4; j++) {
            attn[(size_t)(b * Sx + i0 + ty * 4 + i) * Hx + n * 64 + tx * 4 + j] = acc[i][j];
        }
    }
}

// ---------------- launcher ----------------
extern "C" void kernel_launch(void* const* d_in, const int* in_sizes, int n_in,
                              void* d_out, int out_size) {
    const int*   ids    = (const int*)d_in[0];
    const int*   sp     = (const int*)d_in[1];
    const float* emb    = (const float*)d_in[2];
    const float* ln1_g  = (const float*)d_in[3];
    const float* ln1_b  = (const float*)d_in[4];
    const float* Wqkv   = (const float*)d_in[5];
    const float* bqkv   = (const float*)d_in[6];
    const float* Wo     = (const float*)d_in[7];
    const float* bo     = (const float*)d_in[8];
    const float* ln2_g  = (const float*)d_in[9];
    const float* ln2_b  = (const float*)d_in[10];
    const float* Wfc    = (const float*)d_in[11];
    const float* bfc    = (const float*)d_in[12];
    const float* Wproj  = (const float*)d_in[13];
    const float* bproj  = (const float*)d_in[14];
    const float* lnf_g  = (const float*)d_in[15];
    const float* lnf_b  = (const float*)d_in[16];
    float* out = (float*)d_out;

    float *x, *h, *qkv, *attn, *mid, *scores;
    cudaGetSymbolAddress((void**)&x,      g_x);
    cudaGetSymbolAddress((void**)&h,      g_h);
    cudaGetSymbolAddress((void**)&qkv,    g_qkv);
    cudaGetSymbolAddress((void**)&attn,   g_attn);
    cudaGetSymbolAddress((void**)&mid,    g_mid);
    cudaGetSymbolAddress((void**)&scores, g_scores);

    embed_kernel<<<Mx, 256>>>(ids, emb, x);

    for (int l = 0; l < NLx; l++) {
        ln_kernel<<<Mx, 256>>>(x, ln1_g + l * Hx, ln1_b + l * Hx, h);
        gemm_mma<false, false, false><<<dim3(3 * Hx / 128, Mx / 128), 256>>>(
            h, Wqkv + (size_t)l * Hx * 3 * Hx, bqkv + (size_t)l * 3 * Hx, nullptr, qkv,
            Mx, 3 * Hx, Hx);
        scores_kernel<<<dim3(8, 16, 256), 256>>>(qkv, sp, scores);
        softmax_kernel<<<(Bx * NHx * Sx) / 8, 256>>>(scores);
        pv_kernel<<<dim3(8, 256), 256>>>(scores, qkv, attn);
        gemm_mma<false, false, true><<<dim3(Hx / 128, Mx / 128), 256>>>(
            attn, Wo + (size_t)l * Hx * Hx, bo + (size_t)l * Hx, x, x, Mx, Hx, Hx);
        ln_kernel<<<Mx, 256>>>(x, ln2_g + l * Hx, ln2_b + l * Hx, h);
        gemm_mma<false, true, false><<<dim3(Fx / 128, Mx / 128), 256>>>(
            h, Wfc + (size_t)l * Hx * Fx, bfc + (size_t)l * Fx, nullptr, mid,
            Mx, Fx, Hx);
        gemm_mma<false, false, true><<<dim3(Hx / 128, Mx / 128), 256>>>(
            mid, Wproj + (size_t)l * Fx * Hx, bproj + (size_t)l * Hx, x, x, Mx, Hx, Fx);
    }

    ln_kernel<<<Mx, 256>>>(x, lnf_g, lnf_b, h);
    gemm_mma<true, false, false><<<dim3(Vx / 128, Mx / 128), 256>>>(
        h, emb, nullptr, nullptr, out, Mx, Vx, Hx);
}

// round 3
// speedup vs baseline: 3.6013x; 1.6320x over previous
#include <cuda_runtime.h>
#include <math.h>
#include <stdint.h>

#define Bx  16
#define Sx  512
#define Vx  512
#define Hx  1024
#define NLx 8
#define NHx 16
#define DHx 64
#define Fx  4096
#define Mx  (Bx*Sx)   // 8192 rows of activations

#define LOG2E 1.4426950408889634f

// ---------------- scratch (no allocations allowed) ----------------
__device__ float g_x[Mx*Hx];
__device__ float g_h[Mx*Hx];
__device__ float g_qkv[Mx*3*Hx];
__device__ float g_attn[Mx*Hx];
__device__ float g_mid[(size_t)Mx*Fx];

// ---------------- helpers ----------------
__device__ __forceinline__ float to_tf32(float x) {
    float r;
    asm("cvt.rna.tf32.f32 %0, %1;" : "=f"(r) : "f"(x));
    return r;
}

__device__ __forceinline__ float ex2(float x) {
    float r;
    asm("ex2.approx.f32 %0, %1;" : "=f"(r) : "f"(x));
    return r;
}

__device__ __forceinline__ void mma_tf32(float* c, const uint32_t* a, const uint32_t* b) {
    asm volatile(
        "mma.sync.aligned.m16n8k8.row.col.f32.tf32.tf32.f32 "
        "{%0,%1,%2,%3}, {%4,%5,%6,%7}, {%8,%9}, {%0,%1,%2,%3};\n"
        : "+f"(c[0]), "+f"(c[1]), "+f"(c[2]), "+f"(c[3])
        : "r"(a[0]), "r"(a[1]), "r"(a[2]), "r"(a[3]), "r"(b[0]), "r"(b[1]));
}

__device__ __forceinline__ float gelu_f(float v) {
    return 0.5f * v * (1.0f + tanhf(0.7978845608028654f * (v + 0.044715f * v * v * v)));
}

// ---------------- embedding gather ----------------
__global__ __launch_bounds__(256) void embed_kernel(const int* __restrict__ ids,
                                                    const float* __restrict__ emb,
                                                    float* __restrict__ out) {
    int m = blockIdx.x, t = threadIdx.x;
    int id = ids[m];
    const float4* src = (const float4*)(emb + (size_t)id * Hx);
    float4* dst = (float4*)(out + (size_t)m * Hx);
    dst[t] = src[t];
}

// ---------------- layernorm (row = 1024) ----------------
__global__ __launch_bounds__(256) void ln_kernel(const float* __restrict__ x,
                                                 const float* __restrict__ g,
                                                 const float* __restrict__ b,
                                                 float* __restrict__ out) {
    int m = blockIdx.x, t = threadIdx.x;
    __shared__ float red[8];
    float4 v = ((const float4*)(x + (size_t)m * Hx))[t];

    float s = v.x + v.y + v.z + v.w;
#pragma unroll
    for (int o = 16; o; o >>= 1) s += __shfl_xor_sync(0xffffffffu, s, o);
    if ((t & 31) == 0) red[t >> 5] = s;
    __syncthreads();
    float mu = 0.f;
#pragma unroll
    for (int w = 0; w < 8; w++) mu += red[w];
    mu *= (1.0f / Hx);
    __syncthreads();

    float d0 = v.x - mu, d1 = v.y - mu, d2 = v.z - mu, d3 = v.w - mu;
    float s2 = d0*d0 + d1*d1 + d2*d2 + d3*d3;
#pragma unroll
    for (int o = 16; o; o >>= 1) s2 += __shfl_xor_sync(0xffffffffu, s2, o);
    if ((t & 31) == 0) red[t >> 5] = s2;
    __syncthreads();
    float var = 0.f;
#pragma unroll
    for (int w = 0; w < 8; w++) var += red[w];
    var *= (1.0f / Hx);
    float inv = rsqrtf(var + 1e-5f);

    float4 gg = ((const float4*)g)[t];
    float4 bb = ((const float4*)b)[t];
    float4 o4;
    o4.x = d0 * inv * gg.x + bb.x;
    o4.y = d1 * inv * gg.y + bb.y;
    o4.z = d2 * inv * gg.z + bb.z;
    o4.w = d3 * inv * gg.w + bb.w;
    ((float4*)(out + (size_t)m * Hx))[t] = o4;
}

// ---------------- tf32 tensor-core GEMM: C = f(A@W + bias) (+ resid) --------
#define APAD 36
#define BPAD 136

template<bool TRANSB, bool GELU, bool RESID>
__global__ __launch_bounds__(256) void gemm_mma(const float* __restrict__ A,
                                                const float* __restrict__ W,
                                                const float* __restrict__ bias,
                                                const float* __restrict__ R,
                                                float* __restrict__ C,
                                                int M, int N, int K) {
    __shared__ float As[128 * APAD];
    __shared__ float Bs[32 * BPAD];

    const int t = threadIdx.x;
    const int warp = t >> 5, lane = t & 31;
    const int g = lane >> 2, q = lane & 3;
    const int wm = warp >> 1;
    const int wn = warp & 1;
    const int m0 = blockIdx.y * 128, n0 = blockIdx.x * 128;

    float acc[2][8][4];
#pragma unroll
    for (int mt = 0; mt < 2; mt++)
#pragma unroll
        for (int nt = 0; nt < 8; nt++)
#pragma unroll
            for (int r = 0; r < 4; r++) acc[mt][nt][r] = 0.f;

    for (int k0 = 0; k0 < K; k0 += 32) {
        {
            int rb = t >> 3, c4 = (t & 7) * 4;
#pragma unroll
            for (int p = 0; p < 4; p++) {
                int row = rb + p * 32;
                float4 a = *(const float4*)(A + (size_t)(m0 + row) * K + k0 + c4);
                a.x = to_tf32(a.x); a.y = to_tf32(a.y);
                a.z = to_tf32(a.z); a.w = to_tf32(a.w);
                *(float4*)&As[row * APAD + c4] = a;
            }
        }
        if (!TRANSB) {
            int rb = t >> 5, c = (t & 31) * 4;
#pragma unroll
            for (int p = 0; p < 4; p++) {
                int kr = rb + p * 8;
                float4 b = *(const float4*)(W + (size_t)(k0 + kr) * N + n0 + c);
                b.x = to_tf32(b.x); b.y = to_tf32(b.y);
                b.z = to_tf32(b.z); b.w = to_tf32(b.w);
                *(float4*)&Bs[kr * BPAD + c] = b;
            }
        } else {
            int nb = t >> 3, kc = (t & 7) * 4;
#pragma unroll
            for (int p = 0; p < 4; p++) {
                int nr = nb + p * 32;
                float4 b = *(const float4*)(W + (size_t)(n0 + nr) * K + k0 + kc);
                Bs[(kc + 0) * BPAD + nr] = to_tf32(b.x);
                Bs[(kc + 1) * BPAD + nr] = to_tf32(b.y);
                Bs[(kc + 2) * BPAD + nr] = to_tf32(b.z);
                Bs[(kc + 3) * BPAD + nr] = to_tf32(b.w);
            }
        }
        __syncthreads();

#pragma unroll
        for (int ks = 0; ks < 4; ks++) {
            const int k = ks * 8;
            uint32_t af[2][4], bf[8][2];
#pragma unroll
            for (int mt = 0; mt < 2; mt++) {
                int r = wm * 32 + mt * 16 + g;
                af[mt][0] = __float_as_uint(As[(r    ) * APAD + k + q]);
                af[mt][1] = __float_as_uint(As[(r + 8) * APAD + k + q]);
                af[mt][2] = __float_as_uint(As[(r    ) * APAD + k + q + 4]);
                af[mt][3] = __float_as_uint(As[(r + 8) * APAD + k + q + 4]);
            }
#pragma unroll
            for (int nt = 0; nt < 8; nt++) {
                int n = wn * 64 + nt * 8 + g;
                bf[nt][0] = __float_as_uint(Bs[(k + q    ) * BPAD + n]);
                bf[nt][1] = __float_as_uint(Bs[(k + q + 4) * BPAD + n]);
            }
#pragma unroll
            for (int mt = 0; mt < 2; mt++)
#pragma unroll
                for (int nt = 0; nt < 8; nt++)
                    mma_tf32(acc[mt][nt], af[mt], bf[nt]);
        }
        __syncthreads();
    }

#pragma unroll
    for (int mt = 0; mt < 2; mt++) {
#pragma unroll
        for (int nt = 0; nt < 8; nt++) {
            int r0 = m0 + wm * 32 + mt * 16 + g;
            int c0 = n0 + wn * 64 + nt * 8 + q * 2;
            float b0 = bias ? bias[c0] : 0.f;
            float b1 = bias ? bias[c0 + 1] : 0.f;
#pragma unroll
            for (int half = 0; half < 2; half++) {
                int row = r0 + half * 8;
                float v0 = acc[mt][nt][half * 2 + 0] + b0;
                float v1 = acc[mt][nt][half * 2 + 1] + b1;
                if (GELU) { v0 = gelu_f(v0); v1 = gelu_f(v1); }
                if (RESID) {
                    const float2 rr = *(const float2*)(R + (size_t)row * N + c0);
                    v0 += rr.x; v1 += rr.y;
                }
                float2 o2; o2.x = v0; o2.y = v1;
                *(float2*)(C + (size_t)row * N + c0) = o2;
            }
        }
    }
}

// ---------------- fused flash attention (tf32 mma, online softmax) ----------
// grid: (it=S/64, b*NH). block: 128 threads (4 warps, each 16 q-rows).
// Qs/Ks/Ps stride 68 (bank 4g+q conflict-free frags), Vs stride 72 (8q+g).
#define ATTN_SMEM_FLOATS (64*68*3 + 64*72)

__global__ __launch_bounds__(128) void attn_kernel(const float* __restrict__ qkv,
                                                   const int* __restrict__ sp,
                                                   float* __restrict__ attn) {
    extern __shared__ float sm[];
    float* Qs = sm;                 // [64][68]
    float* Ks = Qs + 64 * 68;       // [64][68]  (key-major, [j][d])
    float* Vs = Ks + 64 * 68;       // [64][72]  ([j][d])
    float* Ps = Vs + 64 * 72;       // [64][68]

    const int it = blockIdx.x, bn = blockIdx.y;
    const int b = bn >> 4, n = bn & 15;
    const int t = threadIdx.x, w = t >> 5, lane = t & 31;
    const int g = lane >> 2, q = lane & 3;
    const int i0 = it * 64;
    const int spv = sp[b];
    const float slope2 = exp2f(-0.5f * (float)(n + 1)) * LOG2E;
    const float qscale = 0.125f * LOG2E;

    // load Q tile (pre-scaled, tf32)
#pragma unroll
    for (int l = 0; l < 8; l++) {
        int e = t + l * 128;
        int row = e >> 4, d4 = (e & 15) * 4;
        float4 v = *(const float4*)(qkv + (size_t)(b * Sx + i0 + row) * 3072 + n * 64 + d4);
        v.x = to_tf32(v.x * qscale); v.y = to_tf32(v.y * qscale);
        v.z = to_tf32(v.z * qscale); v.w = to_tf32(v.w * qscale);
        *(float4*)&Qs[row * 68 + d4] = v;
    }

    float o[8][4];
#pragma unroll
    for (int nt = 0; nt < 8; nt++)
#pragma unroll
        for (int c = 0; c < 4; c++) o[nt][c] = 0.f;
    float m0 = -1e30f, m1 = -1e30f, l0 = 0.f, l1 = 0.f;

    const int r0 = w * 16 + g;
    const int rowA = i0 + r0, rowB = rowA + 8;

    for (int jt = 0; jt <= it; jt++) {
        const int j0 = jt * 64;
        __syncthreads();
#pragma unroll
        for (int l = 0; l < 8; l++) {
            int e = t + l * 128;
            int row = e >> 4, d4 = (e & 15) * 4;
            const float* base = qkv + (size_t)(b * Sx + j0 + row) * 3072 + n * 64 + d4;
            float4 kv = *(const float4*)(base + 1024);
            kv.x = to_tf32(kv.x); kv.y = to_tf32(kv.y);
            kv.z = to_tf32(kv.z); kv.w = to_tf32(kv.w);
            *(float4*)&Ks[row * 68 + d4] = kv;
            float4 vv = *(const float4*)(base + 2048);
            vv.x = to_tf32(vv.x); vv.y = to_tf32(vv.y);
            vv.z = to_tf32(vv.z); vv.w = to_tf32(vv.w);
            *(float4*)&Vs[row * 72 + d4] = vv;
        }
        __syncthreads();

        // ---- QK^T (already in log2 domain via qscale)
        float s[8][4];
#pragma unroll
        for (int nt = 0; nt < 8; nt++)
#pragma unroll
            for (int c = 0; c < 4; c++) s[nt][c] = 0.f;
#pragma unroll
        for (int kk = 0; kk < 8; kk++) {
            const int k = kk * 8;
            uint32_t a[4];
            a[0] = __float_as_uint(Qs[(r0    ) * 68 + k + q]);
            a[1] = __float_as_uint(Qs[(r0 + 8) * 68 + k + q]);
            a[2] = __float_as_uint(Qs[(r0    ) * 68 + k + q + 4]);
            a[3] = __float_as_uint(Qs[(r0 + 8) * 68 + k + q + 4]);
#pragma unroll
            for (int nt = 0; nt < 8; nt++) {
                uint32_t bfr[2];
                bfr[0] = __float_as_uint(Ks[(nt * 8 + g) * 68 + k + q]);
                bfr[1] = __float_as_uint(Ks[(nt * 8 + g) * 68 + k + q + 4]);
                mma_tf32(s[nt], a, bfr);
            }
        }

        // ---- bias + mask (log2 domain)
#pragma unroll
        for (int nt = 0; nt < 8; nt++) {
#pragma unroll
            for (int c = 0; c < 4; c++) {
                int i = (c < 2) ? rowA : rowB;
                int j = j0 + nt * 8 + 2 * q + (c & 1);
                bool allowed = (j <= i) && !((i >= spv) && (j < spv));
                s[nt][c] = allowed ? (s[nt][c] - slope2 * (float)(i - j)) : -1e30f;
            }
        }

        // ---- online softmax
        float mx0 = -1e30f, mx1 = -1e30f;
#pragma unroll
        for (int nt = 0; nt < 8; nt++) {
            mx0 = fmaxf(mx0, fmaxf(s[nt][0], s[nt][1]));
            mx1 = fmaxf(mx1, fmaxf(s[nt][2], s[nt][3]));
        }
        mx0 = fmaxf(mx0, __shfl_xor_sync(0xffffffffu, mx0, 1));
        mx0 = fmaxf(mx0, __shfl_xor_sync(0xffffffffu, mx0, 2));
        mx1 = fmaxf(mx1, __shfl_xor_sync(0xffffffffu, mx1, 1));
        mx1 = fmaxf(mx1, __shfl_xor_sync(0xffffffffu, mx1, 2));
        float mn0 = fmaxf(m0, mx0), mn1 = fmaxf(m1, mx1);
        float al0 = ex2(m0 - mn0), al1 = ex2(m1 - mn1);

        float sum0 = 0.f, sum1 = 0.f;
#pragma unroll
        for (int nt = 0; nt < 8; nt++) {
            float p0 = ex2(s[nt][0] - mn0);
            float p1 = ex2(s[nt][1] - mn0);
            float p2 = ex2(s[nt][2] - mn1);
            float p3 = ex2(s[nt][3] - mn1);
            sum0 += p0 + p1; sum1 += p2 + p3;
            float2 lo2; lo2.x = to_tf32(p0); lo2.y = to_tf32(p1);
            *(float2*)&Ps[(r0    ) * 68 + nt * 8 + 2 * q] = lo2;
            float2 hi2; hi2.x = to_tf32(p2); hi2.y = to_tf32(p3);
            *(float2*)&Ps[(r0 + 8) * 68 + nt * 8 + 2 * q] = hi2;
        }
        sum0 += __shfl_xor_sync(0xffffffffu, sum0, 1);
        sum0 += __shfl_xor_sync(0xffffffffu, sum0, 2);
        sum1 += __shfl_xor_sync(0xffffffffu, sum1, 1);
        sum1 += __shfl_xor_sync(0xffffffffu, sum1, 2);
        l0 = l0 * al0 + sum0;
        l1 = l1 * al1 + sum1;
        m0 = mn0; m1 = mn1;
#pragma unroll
        for (int nt = 0; nt < 8; nt++) {
            o[nt][0] *= al0; o[nt][1] *= al0;
            o[nt][2] *= al1; o[nt][3] *= al1;
        }
        __syncwarp();

        // ---- P @ V
#pragma unroll
        for (int kk = 0; kk < 8; kk++) {
            const int k = kk * 8;
            uint32_t a[4];
            a[0] = __float_as_uint(Ps[(r0    ) * 68 + k + q]);
            a[1] = __float_as_uint(Ps[(r0 + 8) * 68 + k + q]);
            a[2] = __float_as_uint(Ps[(r0    ) * 68 + k + q + 4]);
            a[3] = __float_as_uint(Ps[(r0 + 8) * 68 + k + q + 4]);
#pragma unroll
            for (int nt = 0; nt < 8; nt++) {
                uint32_t bfr[2];
                bfr[0] = __float_as_uint(Vs[(k + q    ) * 72 + nt * 8 + g]);
                bfr[1] = __float_as_uint(Vs[(k + q + 4) * 72 + nt * 8 + g]);
                mma_tf32(o[nt], a, bfr);
            }
        }
    }

    const float inv0 = 1.0f / l0, inv1 = 1.0f / l1;
#pragma unroll
    for (int nt = 0; nt < 8; nt++) {
        float2 v0; v0.x = o[nt][0] * inv0; v0.y = o[nt][1] * inv0;
        *(float2*)(attn + (size_t)(b * Sx + rowA) * Hx + n * 64 + nt * 8 + 2 * q) = v0;
        float2 v1; v1.x = o[nt][2] * inv1; v1.y = o[nt][3] * inv1;
        *(float2*)(attn + (size_t)(b * Sx + rowB) * Hx + n * 64 + nt * 8 + 2 * q) = v1;
    }
}

// ---------------- 3xTF32 logits GEMM: C = A @ emb^T (fp32-accurate) --------
__global__ __launch_bounds__(128) void gemm_logits(const float* __restrict__ A,
                                                   const float* __restrict__ Bm,
                                                   float* __restrict__ C,
                                                   int M, int N, int K) {
    __shared__ float Ah[64 * 36], Al[64 * 36];
    __shared__ float Bh[32 * 72], Bl[32 * 72];
    const int t = threadIdx.x;
    const int warp = t >> 5, lane = t & 31;
    const int g = lane >> 2, q = lane & 3;
    const int wm = warp >> 1, wn = warp & 1;
    const int m0 = blockIdx.y * 64, n0 = blockIdx.x * 64;

    float acc[2][4][4];
#pragma unroll
    for (int mt = 0; mt < 2; mt++)
#pragma unroll
        for (int nt = 0; nt < 4; nt++)
#pragma unroll
            for (int r = 0; r < 4; r++) acc[mt][nt][r] = 0.f;

    for (int k0 = 0; k0 < K; k0 += 32) {
        {   // A 64x32
            int row = t >> 1, c4 = (t & 1) * 16;
#pragma unroll
            for (int p = 0; p < 4; p++) {
                float4 v = *(const float4*)(A + (size_t)(m0 + row) * K + k0 + c4 + p * 4);
                float4 hi, lo;
                hi.x = to_tf32(v.x); lo.x = to_tf32(v.x - hi.x);
                hi.y = to_tf32(v.y); lo.y = to_tf32(v.y - hi.y);
                hi.z = to_tf32(v.z); lo.z = to_tf32(v.z - hi.z);
                hi.w = to_tf32(v.w); lo.w = to_tf32(v.w - hi.w);
                *(float4*)&Ah[row * 36 + c4 + p * 4] = hi;
                *(float4*)&Al[row * 36 + c4 + p * 4] = lo;
            }
        }
        {   // B (emb) 64 rows x 32 k, transposed into Bs[k][n]
#pragma unroll
            for (int p = 0; p < 4; p++) {
                int e = t + p * 128;
                int row = e & 63, c4 = (e >> 6) * 4;
                float4 v = *(const float4*)(Bm + (size_t)(n0 + row) * K + k0 + c4);
                float hv, lv;
                hv = to_tf32(v.x); lv = to_tf32(v.x - hv);
                Bh[(c4 + 0) * 72 + row] = hv; Bl[(c4 + 0) * 72 + row] = lv;
                hv = to_tf32(v.y); lv = to_tf32(v.y - hv);
                Bh[(c4 + 1) * 72 + row] = hv; Bl[(c4 + 1) * 72 + row] = lv;
                hv = to_tf32(v.z); lv = to_tf32(v.z - hv);
                Bh[(c4 + 2) * 72 + row] = hv; Bl[(c4 + 2) * 72 + row] = lv;
                hv = to_tf32(v.w); lv = to_tf32(v.w - hv);
                Bh[(c4 + 3) * 72 + row] = hv; Bl[(c4 + 3) * 72 + row] = lv;
            }
        }
        __syncthreads();

#pragma unroll
        for (int ks = 0; ks < 4; ks++) {
            const int k = ks * 8;
            uint32_t ah[2][4], al[2][4], bh[4][2], bl[4][2];
#pragma unroll
            for (int mt = 0; mt < 2; mt++) {
                int r = wm * 32 + mt * 16 + g;
                ah[mt][0] = __float_as_uint(Ah[(r    ) * 36 + k + q]);
                ah[mt][1] = __float_as_uint(Ah[(r + 8) * 36 + k + q]);
                ah[mt][2] = __float_as_uint(Ah[(r    ) * 36 + k + q + 4]);
                ah[mt][3] = __float_as_uint(Ah[(r + 8) * 36 + k + q + 4]);
                al[mt][0] = __float_as_uint(Al[(r    ) * 36 + k + q]);
                al[mt][1] = __float_as_uint(Al[(r + 8) * 36 + k + q]);
                al[mt][2] = __float_as_uint(Al[(r    ) * 36 + k + q + 4]);
                al[mt][3] = __float_as_uint(Al[(r + 8) * 36 + k + q + 4]);
            }
#pragma unroll
            for (int nt = 0; nt < 4; nt++) {
                int nn = wn * 32 + nt * 8 + g;
                bh[nt][0] = __float_as_uint(Bh[(k + q    ) * 72 + nn]);
                bh[nt][1] = __float_as_uint(Bh[(k + q + 4) * 72 + nn]);
                bl[nt][0] = __float_as_uint(Bl[(k + q    ) * 72 + nn]);
                bl[nt][1] = __float_as_uint(Bl[(k + q + 4) * 72 + nn]);
            }
#pragma unroll
            for (int mt = 0; mt < 2; mt++)
#pragma unroll
                for (int nt = 0; nt < 4; nt++) {
                    mma_tf32(acc[mt][nt], ah[mt], bl[nt]);
                    mma_tf32(acc[mt][nt], al[mt], bh[nt]);
                    mma_tf32(acc[mt][nt], ah[mt], bh[nt]);
                }
        }
        __syncthreads();
    }

#pragma unroll
    for (int mt = 0; mt < 2; mt++) {
#pragma unroll
        for (int nt = 0; nt < 4; nt++) {
            int r0 = m0 + wm * 32 + mt * 16 + g;
            int c0 = n0 + wn * 32 + nt * 8 + q * 2;
#pragma unroll
            for (int half = 0; half < 2; half++) {
                int row = r0 + half * 8;
                float2 o2;
                o2.x = acc[mt][nt][half * 2 + 0];
                o2.y = acc[mt][nt][half * 2 + 1];
                *(float2*)(C + (size_t)row * N + c0) = o2;
            }
        }
    }
}

// ---------------- launcher ----------------
extern "C" void kernel_launch(void* const* d_in, const int* in_sizes, int n_in,
                              void* d_out, int out_size) {
    const int*   ids    = (const int*)d_in[0];
    const int*   sp     = (const int*)d_in[1];
    const float* emb    = (const float*)d_in[2];
    const float* ln1_g  = (const float*)d_in[3];
    const float* ln1_b  = (const float*)d_in[4];
    const float* Wqkv   = (const float*)d_in[5];
    const float* bqkv   = (const float*)d_in[6];
    const float* Wo     = (const float*)d_in[7];
    const float* bo     = (const float*)d_in[8];
    const float* ln2_g  = (const float*)d_in[9];
    const float* ln2_b  = (const float*)d_in[10];
    const float* Wfc    = (const float*)d_in[11];
    const float* bfc    = (const float*)d_in[12];
    const float* Wproj  = (const float*)d_in[13];
    const float* bproj  = (const float*)d_in[14];
    const float* lnf_g  = (const float*)d_in[15];
    const float* lnf_b  = (const float*)d_in[16];
    float* out = (float*)d_out;

    float *x, *h, *qkv, *attn, *mid;
    cudaGetSymbolAddress((void**)&x,    g_x);
    cudaGetSymbolAddress((void**)&h,    g_h);
    cudaGetSymbolAddress((void**)&qkv,  g_qkv);
    cudaGetSymbolAddress((void**)&attn, g_attn);
    cudaGetSymbolAddress((void**)&mid,  g_mid);

    const int attn_smem = ATTN_SMEM_FLOATS * 4;
    cudaFuncSetAttribute(attn_kernel, cudaFuncAttributeMaxDynamicSharedMemorySize, attn_smem);

    embed_kernel<<<Mx, 256>>>(ids, emb, x);

    for (int l = 0; l < NLx; l++) {
        ln_kernel<<<Mx, 256>>>(x, ln1_g + l * Hx, ln1_b + l * Hx, h);
        gemm_mma<false, false, false><<<dim3(3 * Hx / 128, Mx / 128), 256>>>(
            h, Wqkv + (size_t)l * Hx * 3 * Hx, bqkv + (size_t)l * 3 * Hx, nullptr, qkv,
            Mx, 3 * Hx, Hx);
        attn_kernel<<<dim3(Sx / 64, Bx * NHx), 128, attn_smem>>>(qkv, sp, attn);
        gemm_mma<false, false, true><<<dim3(Hx / 128, Mx / 128), 256>>>(
            attn, Wo + (size_t)l * Hx * Hx, bo + (size_t)l * Hx, x, x, Mx, Hx, Hx);
        ln_kernel<<<Mx, 256>>>(x, ln2_g + l * Hx, ln2_b + l * Hx, h);
        gemm_mma<false, true, false><<<dim3(Fx / 128, Mx / 128), 256>>>(
            h, Wfc + (size_t)l * Hx * Fx, bfc + (size_t)l * Fx, nullptr, mid,
            Mx, Fx, Hx);
        gemm_mma<false, false, true><<<dim3(Hx / 128, Mx / 128), 256>>>(
            mid, Wproj + (size_t)l * Fx * Hx, bproj + (size_t)l * Hx, x, x, Mx, Hx, Fx);
    }

    ln_kernel<<<Mx, 256>>>(x, lnf_g, lnf_b, h);
    gemm_logits<<<dim3(Vx / 64, Mx / 64), 128>>>(h, emb, out, Mx, Vx, Hx);
}

// round 4
// speedup vs baseline: 3.7713x; 1.0472x over previous
#include <cuda_runtime.h>
#include <math.h>
#include <stdint.h>

#define Bx  16
#define Sx  512
#define Vx  512
#define Hx  1024
#define NLx 8
#define NHx 16
#define DHx 64
#define Fx  4096
#define Mx  (Bx*Sx)   // 8192 rows of activations

#define LOG2E 1.4426950408889634f

// ---------------- scratch (no allocations allowed) ----------------
__device__ float g_x[Mx*Hx];
__device__ float g_h[Mx*Hx];
__device__ float g_qkv[Mx*3*Hx];
__device__ float g_attn[Mx*Hx];
__device__ float g_mid[(size_t)Mx*Fx];

// ---------------- helpers ----------------
__device__ __forceinline__ float to_tf32(float x) {
    float r;
    asm("cvt.rna.tf32.f32 %0, %1;" : "=f"(r) : "f"(x));
    return r;
}

__device__ __forceinline__ uint32_t frag_tf32(float x) {
    float r;
    asm("cvt.rna.tf32.f32 %0, %1;" : "=f"(r) : "f"(x));
    return __float_as_uint(r);
}

__device__ __forceinline__ float ex2(float x) {
    float r;
    asm("ex2.approx.f32 %0, %1;" : "=f"(r) : "f"(x));
    return r;
}

__device__ __forceinline__ void mma_tf32(float* c, const uint32_t* a, const uint32_t* b) {
    asm volatile(
        "mma.sync.aligned.m16n8k8.row.col.f32.tf32.tf32.f32 "
        "{%0,%1,%2,%3}, {%4,%5,%6,%7}, {%8,%9}, {%0,%1,%2,%3};\n"
        : "+f"(c[0]), "+f"(c[1]), "+f"(c[2]), "+f"(c[3])
        : "r"(a[0]), "r"(a[1]), "r"(a[2]), "r"(a[3]), "r"(b[0]), "r"(b[1]));
}

__device__ __forceinline__ void cp_async16(float* smem_dst, const float* gmem_src) {
    uint32_t s = (uint32_t)__cvta_generic_to_shared(smem_dst);
    asm volatile("cp.async.cg.shared.global [%0], [%1], 16;\n" :: "r"(s), "l"(gmem_src));
}
__device__ __forceinline__ void cp_commit() {
    asm volatile("cp.async.commit_group;\n");
}
__device__ __forceinline__ void cp_wait0() {
    asm volatile("cp.async.wait_group 0;\n");
}

__device__ __forceinline__ float gelu_f(float v) {
    return 0.5f * v * (1.0f + tanhf(0.7978845608028654f * (v + 0.044715f * v * v * v)));
}

// ---------------- embedding gather ----------------
__global__ __launch_bounds__(256) void embed_kernel(const int* __restrict__ ids,
                                                    const float* __restrict__ emb,
                                                    float* __restrict__ out) {
    int m = blockIdx.x, t = threadIdx.x;
    int id = ids[m];
    const float4* src = (const float4*)(emb + (size_t)id * Hx);
    float4* dst = (float4*)(out + (size_t)m * Hx);
    dst[t] = src[t];
}

// ---------------- layernorm (row = 1024) ----------------
__global__ __launch_bounds__(256) void ln_kernel(const float* __restrict__ x,
                                                 const float* __restrict__ g,
                                                 const float* __restrict__ b,
                                                 float* __restrict__ out) {
    int m = blockIdx.x, t = threadIdx.x;
    __shared__ float red[8];
    float4 v = ((const float4*)(x + (size_t)m * Hx))[t];

    float s = v.x + v.y + v.z + v.w;
#pragma unroll
    for (int o = 16; o; o >>= 1) s += __shfl_xor_sync(0xffffffffu, s, o);
    if ((t & 31) == 0) red[t >> 5] = s;
    __syncthreads();
    float mu = 0.f;
#pragma unroll
    for (int w = 0; w < 8; w++) mu += red[w];
    mu *= (1.0f / Hx);
    __syncthreads();

    float d0 = v.x - mu, d1 = v.y - mu, d2 = v.z - mu, d3 = v.w - mu;
    float s2 = d0*d0 + d1*d1 + d2*d2 + d3*d3;
#pragma unroll
    for (int o = 16; o; o >>= 1) s2 += __shfl_xor_sync(0xffffffffu, s2, o);
    if ((t & 31) == 0) red[t >> 5] = s2;
    __syncthreads();
    float var = 0.f;
#pragma unroll
    for (int w = 0; w < 8; w++) var += red[w];
    var *= (1.0f / Hx);
    float inv = rsqrtf(var + 1e-5f);

    float4 gg = ((const float4*)g)[t];
    float4 bb = ((const float4*)b)[t];
    float4 o4;
    o4.x = d0 * inv * gg.x + bb.x;
    o4.y = d1 * inv * gg.y + bb.y;
    o4.z = d2 * inv * gg.z + bb.z;
    o4.w = d3 * inv * gg.w + bb.w;
    ((float4*)(out + (size_t)m * Hx))[t] = o4;
}

// ------- tf32 tensor-core GEMM, cp.async 2-stage pipeline -------------------
// A: [M,K] row-major, W: [K,N]. CTA tile 128x128x32. fp32 in smem; tf32 cvt at
// fragment load (precision identical to cvt-at-fill).
#define APAD 36
#define BPAD 136

template<bool GELU, bool RESID>
__global__ __launch_bounds__(256) void gemm_mma(const float* __restrict__ A,
                                                const float* __restrict__ W,
                                                const float* __restrict__ bias,
                                                const float* __restrict__ R,
                                                float* __restrict__ C,
                                                int M, int N, int K) {
    __shared__ float As[2][128 * APAD];
    __shared__ float Bs[2][32 * BPAD];

    const int t = threadIdx.x;
    const int warp = t >> 5, lane = t & 31;
    const int g = lane >> 2, q = lane & 3;
    const int wm = warp >> 1;
    const int wn = warp & 1;
    const int m0 = blockIdx.y * 128, n0 = blockIdx.x * 128;

    const int a_rb = t >> 3, a_c4 = (t & 7) * 4;     // A: 4 chunks of rows +32p
    const int b_rb = t >> 5, b_c = (t & 31) * 4;     // B: 4 chunks of k-rows +8p

    float acc[2][8][4];
#pragma unroll
    for (int mt = 0; mt < 2; mt++)
#pragma unroll
        for (int nt = 0; nt < 8; nt++)
#pragma unroll
            for (int r = 0; r < 4; r++) acc[mt][nt][r] = 0.f;

    // ---- prologue: prefetch tile 0 into stage 0
#pragma unroll
    for (int p = 0; p < 4; p++) {
        int row = a_rb + p * 32;
        cp_async16(&As[0][row * APAD + a_c4], A + (size_t)(m0 + row) * K + a_c4);
    }
#pragma unroll
    for (int p = 0; p < 4; p++) {
        int kr = b_rb + p * 8;
        cp_async16(&Bs[0][kr * BPAD + b_c], W + (size_t)kr * N + n0 + b_c);
    }
    cp_commit();

    int cur = 0;
    for (int k0 = 0; k0 < K; k0 += 32) {
        cp_wait0();
        __syncthreads();

        // ---- prefetch next tile into the other stage (overlaps mma below)
        if (k0 + 32 < K) {
            const int kn = k0 + 32;
#pragma unroll
            for (int p = 0; p < 4; p++) {
                int row = a_rb + p * 32;
                cp_async16(&As[cur ^ 1][row * APAD + a_c4],
                           A + (size_t)(m0 + row) * K + kn + a_c4);
            }
#pragma unroll
            for (int p = 0; p < 4; p++) {
                int kr = b_rb + p * 8;
                cp_async16(&Bs[cur ^ 1][kr * BPAD + b_c],
                           W + (size_t)(kn + kr) * N + n0 + b_c);
            }
            cp_commit();
        }

        const float* Ac = As[cur];
        const float* Bc = Bs[cur];
#pragma unroll
        for (int ks = 0; ks < 4; ks++) {
            const int k = ks * 8;
            uint32_t af[2][4], bf[8][2];
#pragma unroll
            for (int mt = 0; mt < 2; mt++) {
                int r = wm * 32 + mt * 16 + g;
                af[mt][0] = frag_tf32(Ac[(r    ) * APAD + k + q]);
                af[mt][1] = frag_tf32(Ac[(r + 8) * APAD + k + q]);
                af[mt][2] = frag_tf32(Ac[(r    ) * APAD + k + q + 4]);
                af[mt][3] = frag_tf32(Ac[(r + 8) * APAD + k + q + 4]);
            }
#pragma unroll
            for (int nt = 0; nt < 8; nt++) {
                int n = wn * 64 + nt * 8 + g;
                bf[nt][0] = frag_tf32(Bc[(k + q    ) * BPAD + n]);
                bf[nt][1] = frag_tf32(Bc[(k + q + 4) * BPAD + n]);
            }
#pragma unroll
            for (int mt = 0; mt < 2; mt++)
#pragma unroll
                for (int nt = 0; nt < 8; nt++)
                    mma_tf32(acc[mt][nt], af[mt], bf[nt]);
        }
        cur ^= 1;
    }

    // ---- epilogue
#pragma unroll
    for (int mt = 0; mt < 2; mt++) {
#pragma unroll
        for (int nt = 0; nt < 8; nt++) {
            int r0 = m0 + wm * 32 + mt * 16 + g;
            int c0 = n0 + wn * 64 + nt * 8 + q * 2;
            float b0 = bias ? bias[c0] : 0.f;
            float b1 = bias ? bias[c0 + 1] : 0.f;
#pragma unroll
            for (int half = 0; half < 2; half++) {
                int row = r0 + half * 8;
                float v0 = acc[mt][nt][half * 2 + 0] + b0;
                float v1 = acc[mt][nt][half * 2 + 1] + b1;
                if (GELU) { v0 = gelu_f(v0); v1 = gelu_f(v1); }
                if (RESID) {
                    const float2 rr = *(const float2*)(R + (size_t)row * N + c0);
                    v0 += rr.x; v1 += rr.y;
                }
                float2 o2; o2.x = v0; o2.y = v1;
                *(float2*)(C + (size_t)row * N + c0) = o2;
            }
        }
    }
}

// ---------------- fused flash attention (tf32 mma, online softmax) ----------
#define ATTN_SMEM_FLOATS (64*68*3 + 64*72)

__global__ __launch_bounds__(128) void attn_kernel(const float* __restrict__ qkv,
                                                   const int* __restrict__ sp,
                                                   float* __restrict__ attn) {
    extern __shared__ float sm[];
    float* Qs = sm;                 // [64][68]
    float* Ks = Qs + 64 * 68;       // [64][68]
    float* Vs = Ks + 64 * 68;       // [64][72]
    float* Ps = Vs + 64 * 72;       // [64][68]

    const int it = blockIdx.x, bn = blockIdx.y;
    const int b = bn >> 4, n = bn & 15;
    const int t = threadIdx.x, w = t >> 5, lane = t & 31;
    const int g = lane >> 2, q = lane & 3;
    const int i0 = it * 64;
    const int spv = sp[b];
    const float slope2 = exp2f(-0.5f * (float)(n + 1)) * LOG2E;
    const float qscale = 0.125f * LOG2E;

#pragma unroll
    for (int l = 0; l < 8; l++) {
        int e = t + l * 128;
        int row = e >> 4, d4 = (e & 15) * 4;
        float4 v = *(const float4*)(qkv + (size_t)(b * Sx + i0 + row) * 3072 + n * 64 + d4);
        v.x = to_tf32(v.x * qscale); v.y = to_tf32(v.y * qscale);
        v.z = to_tf32(v.z * qscale); v.w = to_tf32(v.w * qscale);
        *(float4*)&Qs[row * 68 + d4] = v;
    }

    float o[8][4];
#pragma unroll
    for (int nt = 0; nt < 8; nt++)
#pragma unroll
        for (int c = 0; c < 4; c++) o[nt][c] = 0.f;
    float m0 = -1e30f, m1 = -1e30f, l0 = 0.f, l1 = 0.f;

    const int r0 = w * 16 + g;
    const int rowA = i0 + r0, rowB = rowA + 8;

    for (int jt = 0; jt <= it; jt++) {
        const int j0 = jt * 64;
        __syncthreads();
#pragma unroll
        for (int l = 0; l < 8; l++) {
            int e = t + l * 128;
            int row = e >> 4, d4 = (e & 15) * 4;
            const float* base = qkv + (size_t)(b * Sx + j0 + row) * 3072 + n * 64 + d4;
            float4 kv = *(const float4*)(base + 1024);
            kv.x = to_tf32(kv.x); kv.y = to_tf32(kv.y);
            kv.z = to_tf32(kv.z); kv.w = to_tf32(kv.w);
            *(float4*)&Ks[row * 68 + d4] = kv;
            float4 vv = *(const float4*)(base + 2048);
            vv.x = to_tf32(vv.x); vv.y = to_tf32(vv.y);
            vv.z = to_tf32(vv.z); vv.w = to_tf32(vv.w);
            *(float4*)&Vs[row * 72 + d4] = vv;
        }
        __syncthreads();

        float s[8][4];
#pragma unroll
        for (int nt = 0; nt < 8; nt++)
#pragma unroll
            for (int c = 0; c < 4; c++) s[nt][c] = 0.f;
#pragma unroll
        for (int kk = 0; kk < 8; kk++) {
            const int k = kk * 8;
            uint32_t a[4];
            a[0] = __float_as_uint(Qs[(r0    ) * 68 + k + q]);
            a[1] = __float_as_uint(Qs[(r0 + 8) * 68 + k + q]);
            a[2] = __float_as_uint(Qs[(r0    ) * 68 + k + q + 4]);
            a[3] = __float_as_uint(Qs[(r0 + 8) * 68 + k + q + 4]);
#pragma unroll
            for (int nt = 0; nt < 8; nt++) {
                uint32_t bfr[2];
                bfr[0] = __float_as_uint(Ks[(nt * 8 + g) * 68 + k + q]);
                bfr[1] = __float_as_uint(Ks[(nt * 8 + g) * 68 + k + q + 4]);
                mma_tf32(s[nt], a, bfr);
            }
        }

#pragma unroll
        for (int nt = 0; nt < 8; nt++) {
#pragma unroll
            for (int c = 0; c < 4; c++) {
                int i = (c < 2) ? rowA : rowB;
                int j = j0 + nt * 8 + 2 * q + (c & 1);
                bool allowed = (j <= i) && !((i >= spv) && (j < spv));
                s[nt][c] = allowed ? (s[nt][c] - slope2 * (float)(i - j)) : -1e30f;
            }
        }

        float mx0 = -1e30f, mx1 = -1e30f;
#pragma unroll
        for (int nt = 0; nt < 8; nt++) {
            mx0 = fmaxf(mx0, fmaxf(s[nt][0], s[nt][1]));
            mx1 = fmaxf(mx1, fmaxf(s[nt][2], s[nt][3]));
        }
        mx0 = fmaxf(mx0, __shfl_xor_sync(0xffffffffu, mx0, 1));
        mx0 = fmaxf(mx0, __shfl_xor_sync(0xffffffffu, mx0, 2));
        mx1 = fmaxf(mx1, __shfl_xor_sync(0xffffffffu, mx1, 1));
        mx1 = fmaxf(mx1, __shfl_xor_sync(0xffffffffu, mx1, 2));
        float mn0 = fmaxf(m0, mx0), mn1 = fmaxf(m1, mx1);
        float al0 = ex2(m0 - mn0), al1 = ex2(m1 - mn1);

        float sum0 = 0.f, sum1 = 0.f;
#pragma unroll
        for (int nt = 0; nt < 8; nt++) {
            float p0 = ex2(s[nt][0] - mn0);
            float p1 = ex2(s[nt][1] - mn0);
            float p2 = ex2(s[nt][2] - mn1);
            float p3 = ex2(s[nt][3] - mn1);
            sum0 += p0 + p1; sum1 += p2 + p3;
            float2 lo2; lo2.x = to_tf32(p0); lo2.y = to_tf32(p1);
            *(float2*)&Ps[(r0    ) * 68 + nt * 8 + 2 * q] = lo2;
            float2 hi2; hi2.x = to_tf32(p2); hi2.y = to_tf32(p3);
            *(float2*)&Ps[(r0 + 8) * 68 + nt * 8 + 2 * q] = hi2;
        }
        sum0 += __shfl_xor_sync(0xffffffffu, sum0, 1);
        sum0 += __shfl_xor_sync(0xffffffffu, sum0, 2);
        sum1 += __shfl_xor_sync(0xffffffffu, sum1, 1);
        sum1 += __shfl_xor_sync(0xffffffffu, sum1, 2);
        l0 = l0 * al0 + sum0;
        l1 = l1 * al1 + sum1;
        m0 = mn0; m1 = mn1;
#pragma unroll
        for (int nt = 0; nt < 8; nt++) {
            o[nt][0] *= al0; o[nt][1] *= al0;
            o[nt][2] *= al1; o[nt][3] *= al1;
        }
        __syncwarp();

#pragma unroll
        for (int kk = 0; kk < 8; kk++) {
            const int k = kk * 8;
            uint32_t a[4];
            a[0] = __float_as_uint(Ps[(r0    ) * 68 + k + q]);
            a[1] = __float_as_uint(Ps[(r0 + 8) * 68 + k + q]);
            a[2] = __float_as_uint(Ps[(r0    ) * 68 + k + q + 4]);
            a[3] = __float_as_uint(Ps[(r0 + 8) * 68 + k + q + 4]);
#pragma unroll
            for (int nt = 0; nt < 8; nt++) {
                uint32_t bfr[2];
                bfr[0] = __float_as_uint(Vs[(k + q    ) * 72 + nt * 8 + g]);
                bfr[1] = __float_as_uint(Vs[(k + q + 4) * 72 + nt * 8 + g]);
                mma_tf32(o[nt], a, bfr);
            }
        }
    }

    const float inv0 = 1.0f / l0, inv1 = 1.0f / l1;
#pragma unroll
    for (int nt = 0; nt < 8; nt++) {
        float2 v0; v0.x = o[nt][0] * inv0; v0.y = o[nt][1] * inv0;
        *(float2*)(attn + (size_t)(b * Sx + rowA) * Hx + n * 64 + nt * 8 + 2 * q) = v0;
        float2 v1; v1.x = o[nt][2] * inv1; v1.y = o[nt][3] * inv1;
        *(float2*)(attn + (size_t)(b * Sx + rowB) * Hx + n * 64 + nt * 8 + 2 * q) = v1;
    }
}

// ---------------- 3xTF32 logits GEMM: C = A @ emb^T (fp32-accurate) --------
__global__ __launch_bounds__(128) void gemm_logits(const float* __restrict__ A,
                                                   const float* __restrict__ Bm,
                                                   float* __restrict__ C,
                                                   int M, int N, int K) {
    __shared__ float Ah[64 * 36], Al[64 * 36];
    __shared__ float Bh[32 * 72], Bl[32 * 72];
    const int t = threadIdx.x;
    const int warp = t >> 5, lane = t & 31;
    const int g = lane >> 2, q = lane & 3;
    const int wm = warp >> 1, wn = warp & 1;
    const int m0 = blockIdx.y * 64, n0 = blockIdx.x * 64;

    float acc[2][4][4];
#pragma unroll
    for (int mt = 0; mt < 2; mt++)
#pragma unroll
        for (int nt = 0; nt < 4; nt++)
#pragma unroll
            for (int r = 0; r < 4; r++) acc[mt][nt][r] = 0.f;

    for (int k0 = 0; k0 < K; k0 += 32) {
        {
            int row = t >> 1, c4 = (t & 1) * 16;
#pragma unroll
            for (int p = 0; p < 4; p++) {
                float4 v = *(const float4*)(A + (size_t)(m0 + row) * K + k0 + c4 + p * 4);
                float4 hi, lo;
                hi.x = to_tf32(v.x); lo.x = to_tf32(v.x - hi.x);
                hi.y = to_tf32(v.y); lo.y = to_tf32(v.y - hi.y);
                hi.z = to_tf32(v.z); lo.z = to_tf32(v.z - hi.z);
                hi.w = to_tf32(v.w); lo.w = to_tf32(v.w - hi.w);
                *(float4*)&Ah[row * 36 + c4 + p * 4] = hi;
                *(float4*)&Al[row * 36 + c4 + p * 4] = lo;
            }
        }
        {
#pragma unroll
            for (int p = 0; p < 4; p++) {
                int e = t + p * 128;
                int row = e & 63, c4 = (e >> 6) * 4;
                float4 v = *(const float4*)(Bm + (size_t)(n0 + row) * K + k0 + c4);
                float hv, lv;
                hv = to_tf32(v.x); lv = to_tf32(v.x - hv);
                Bh[(c4 + 0) * 72 + row] = hv; Bl[(c4 + 0) * 72 + row] = lv;
                hv = to_tf32(v.y); lv = to_tf32(v.y - hv);
                Bh[(c4 + 1) * 72 + row] = hv; Bl[(c4 + 1) * 72 + row] = lv;
                hv = to_tf32(v.z); lv = to_tf32(v.z - hv);
                Bh[(c4 + 2) * 72 + row] = hv; Bl[(c4 + 2) * 72 + row] = lv;
                hv = to_tf32(v.w); lv = to_tf32(v.w - hv);
                Bh[(c4 + 3) * 72 + row] = hv; Bl[(c4 + 3) * 72 + row] = lv;
            }
        }
        __syncthreads();

#pragma unroll
        for (int ks = 0; ks < 4; ks++) {
            const int k = ks * 8;
            uint32_t ah[2][4], al[2][4], bh[4][2], bl[4][2];
#pragma unroll
            for (int mt = 0; mt < 2; mt++) {
                int r = wm * 32 + mt * 16 + g;
                ah[mt][0] = __float_as_uint(Ah[(r    ) * 36 + k + q]);
                ah[mt][1] = __float_as_uint(Ah[(r + 8) * 36 + k + q]);
                ah[mt][2] = __float_as_uint(Ah[(r    ) * 36 + k + q + 4]);
                ah[mt][3] = __float_as_uint(Ah[(r + 8) * 36 + k + q + 4]);
                al[mt][0] = __float_as_uint(Al[(r    ) * 36 + k + q]);
                al[mt][1] = __float_as_uint(Al[(r + 8) * 36 + k + q]);
                al[mt][2] = __float_as_uint(Al[(r    ) * 36 + k + q + 4]);
                al[mt][3] = __float_as_uint(Al[(r + 8) * 36 + k + q + 4]);
            }
#pragma unroll
            for (int nt = 0; nt < 4; nt++) {
                int nn = wn * 32 + nt * 8 + g;
                bh[nt][0] = __float_as_uint(Bh[(k + q    ) * 72 + nn]);
                bh[nt][1] = __float_as_uint(Bh[(k + q + 4) * 72 + nn]);
                bl[nt][0] = __float_as_uint(Bl[(k + q    ) * 72 + nn]);
                bl[nt][1] = __float_as_uint(Bl[(k + q + 4) * 72 + nn]);
            }
#pragma unroll
            for (int mt = 0; mt < 2; mt++)
#pragma unroll
                for (int nt = 0; nt < 4; nt++) {
                    mma_tf32(acc[mt][nt], ah[mt], bl[nt]);
                    mma_tf32(acc[mt][nt], al[mt], bh[nt]);
                    mma_tf32(acc[mt][nt], ah[mt], bh[nt]);
                }
        }
        __syncthreads();
    }

#pragma unroll
    for (int mt = 0; mt < 2; mt++) {
#pragma unroll
        for (int nt = 0; nt < 4; nt++) {
            int r0 = m0 + wm * 32 + mt * 16 + g;
            int c0 = n0 + wn * 32 + nt * 8 + q * 2;
#pragma unroll
            for (int half = 0; half < 2; half++) {
                int row = r0 + half * 8;
                float2 o2;
                o2.x = acc[mt][nt][half * 2 + 0];
                o2.y = acc[mt][nt][half * 2 + 1];
                *(float2*)(C + (size_t)row * N + c0) = o2;
            }
        }
    }
}

// ---------------- launcher ----------------
extern "C" void kernel_launch(void* const* d_in, const int* in_sizes, int n_in,
                              void* d_out, int out_size) {
    const int*   ids    = (const int*)d_in[0];
    const int*   sp     = (const int*)d_in[1];
    const float* emb    = (const float*)d_in[2];
    const float* ln1_g  = (const float*)d_in[3];
    const float* ln1_b  = (const float*)d_in[4];
    const float* Wqkv   = (const float*)d_in[5];
    const float* bqkv   = (const float*)d_in[6];
    const float* Wo     = (const float*)d_in[7];
    const float* bo     = (const float*)d_in[8];
    const float* ln2_g  = (const float*)d_in[9];
    const float* ln2_b  = (const float*)d_in[10];
    const float* Wfc    = (const float*)d_in[11];
    const float* bfc    = (const float*)d_in[12];
    const float* Wproj  = (const float*)d_in[13];
    const float* bproj  = (const float*)d_in[14];
    const float* lnf_g  = (const float*)d_in[15];
    const float* lnf_b  = (const float*)d_in[16];
    float* out = (float*)d_out;

    float *x, *h, *qkv, *attn, *mid;
    cudaGetSymbolAddress((void**)&x,    g_x);
    cudaGetSymbolAddress((void**)&h,    g_h);
    cudaGetSymbolAddress((void**)&qkv,  g_qkv);
    cudaGetSymbolAddress((void**)&attn, g_attn);
    cudaGetSymbolAddress((void**)&mid,  g_mid);

    const int attn_smem = ATTN_SMEM_FLOATS * 4;
    cudaFuncSetAttribute(attn_kernel, cudaFuncAttributeMaxDynamicSharedMemorySize, attn_smem);

    embed_kernel<<<Mx, 256>>>(ids, emb, x);

    for (int l = 0; l < NLx; l++) {
        ln_kernel<<<Mx, 256>>>(x, ln1_g + l * Hx, ln1_b + l * Hx, h);
        gemm_mma<false, false><<<dim3(3 * Hx / 128, Mx / 128), 256>>>(
            h, Wqkv + (size_t)l * Hx * 3 * Hx, bqkv + (size_t)l * 3 * Hx, nullptr, qkv,
            Mx, 3 * Hx, Hx);
        attn_kernel<<<dim3(Sx / 64, Bx * NHx), 128, attn_smem>>>(qkv, sp, attn);
        gemm_mma<false, true><<<dim3(Hx / 128, Mx / 128), 256>>>(
            attn, Wo + (size_t)l * Hx * Hx, bo + (size_t)l * Hx, x, x, Mx, Hx, Hx);
        ln_kernel<<<Mx, 256>>>(x, ln2_g + l * Hx, ln2_b + l * Hx, h);
        gemm_mma<true, false><<<dim3(Fx / 128, Mx / 128), 256>>>(
            h, Wfc + (size_t)l * Hx * Fx, bfc + (size_t)l * Fx, nullptr, mid,
            Mx, Fx, Hx);
        gemm_mma<false, true><<<dim3(Hx / 128, Mx / 128), 256>>>(
            mid, Wproj + (size_t)l * Fx * Hx, bproj + (size_t)l * Hx, x, x, Mx, Hx, Fx);
    }

    ln_kernel<<<Mx, 256>>>(x, lnf_g, lnf_b, h);
    gemm_logits<<<dim3(Vx / 64, Mx / 64), 128>>>(h, emb, out, Mx, Vx, Hx);
}